// round 2
// baseline (speedup 1.0000x reference)
#include <cuda_runtime.h>
#include <math.h>

// Problem constants: x[B=4][C=64][N=4096], W0/W1 [64][64], out [4][4096][64]
#define THR 0.005f
#define EPSI 1e-5f

typedef unsigned long long ull;

// ---------------- device scratch (no cudaMalloc allowed) ----------------
__device__ __align__(16) float    g_xt[4 * 4096 * 64];   // x transposed [b][n][c]
__device__ __align__(16) float    g_x1[4 * 4096 * 64];   // layer-1 output
__device__ __align__(16) float    g_snorm[4 * 4096];     // per-node L2 norm
__device__ __align__(16) float    g_dinv[4 * 4096];      // 1/sqrt(deg)
__device__ __align__(16) int      g_deg[4 * 4096];
__device__ __align__(16) unsigned g_adj[4 * 4096 * 128]; // adjacency bitmask

// ---------------- packed fp32x2 helpers ----------------
__device__ __forceinline__ void fma2(ull& d, ull a, ull b) {
    asm("fma.rn.f32x2 %0, %1, %2, %0;" : "+l"(d) : "l"(a), "l"(b));
}
__device__ __forceinline__ ull pack2(float x) {
    ull r; asm("mov.b64 %0, {%1, %1};" : "=l"(r) : "f"(x)); return r;
}
union F2U { ull u; float2 f; };

// ---------------- trivial kernels ----------------
__global__ void k_zero_deg() {
    int i = blockIdx.x * 256 + threadIdx.x;
    if (i < 4 * 4096) g_deg[i] = 0;
}

__global__ void k_transpose(const float* __restrict__ x) {
    __shared__ float t[32][33];
    int b = blockIdx.z, c0 = blockIdx.y * 32, n0 = blockIdx.x * 32;
    int tx = threadIdx.x, ty = threadIdx.y;
    const float* xp = x + ((b * 64 + c0) * 4096) + n0;
    #pragma unroll
    for (int i = ty; i < 32; i += 8) t[i][tx] = xp[i * 4096 + tx];
    __syncthreads();
    float* op = g_xt + ((b * 4096 + n0) * 64) + c0;
    #pragma unroll
    for (int i = ty; i < 32; i += 8) op[i * 64 + tx] = t[tx][i];
}

__global__ void k_norm() {
    int i = blockIdx.x * 256 + threadIdx.x;   // node over B*N
    if (i >= 4 * 4096) return;
    const float4* p = (const float4*)(g_xt + i * 64);
    float s = 0.f;
    #pragma unroll
    for (int j = 0; j < 16; j++) {
        float4 v = p[j];
        s += v.x * v.x + v.y * v.y + v.z * v.z + v.w * v.w;
    }
    g_snorm[i] = sqrtf(s);
}

__global__ void k_dinv() {
    int i = blockIdx.x * 256 + threadIdx.x;
    if (i < 4 * 4096) g_dinv[i] = 1.0f / sqrtf((float)g_deg[i]);
}

// ---------------- Gram + threshold + degree ----------------
// Block: 64(n) x 64(m) output tile, K=64, 256 threads = 8 warps.
// warp w: m-window = (w&1)*32 (lane -> m), n-range = (w>>1)*16 .. +15.
// Bits assembled with __ballot_sync -> adjacency word directly.
__global__ void __launch_bounds__(256) k_gram(const float* __restrict__ x) {
    __shared__ __align__(16) float As[64][64];
    __shared__ __align__(16) float Bs[64][64];
    __shared__ float sn[64], smn[64];
    __shared__ int sdeg[64];

    int b = blockIdx.z, n0 = blockIdx.y * 64, m0 = blockIdx.x * 64;
    int t = threadIdx.x;
    {
        int c = t >> 2, q = t & 3;
        const float* xb = x + (b * 64 + c) * 4096;
        float4* ar = (float4*)&As[c][q * 16];
        float4* br = (float4*)&Bs[c][q * 16];
        const float4* ag = (const float4*)(xb + n0 + q * 16);
        const float4* bg = (const float4*)(xb + m0 + q * 16);
        #pragma unroll
        for (int j = 0; j < 4; j++) { ar[j] = ag[j]; br[j] = bg[j]; }
    }
    if (t < 64) {
        sn[t]  = g_snorm[b * 4096 + n0 + t];
        smn[t] = g_snorm[b * 4096 + m0 + t];
        sdeg[t] = 0;
    }
    __syncthreads();

    int warp = t >> 5, lane = t & 31;
    int mwin = (warp & 1) * 32, ng = (warp >> 1) * 16;
    int mcol = mwin + lane;

    ull acc[8];
    #pragma unroll
    for (int p = 0; p < 8; p++) acc[p] = 0ULL;

    #pragma unroll 8
    for (int c = 0; c < 64; c++) {
        ull b2 = pack2(Bs[c][mcol]);
        const ulonglong2* ap = (const ulonglong2*)&As[c][ng];
        #pragma unroll
        for (int q = 0; q < 4; q++) {
            ulonglong2 a = ap[q];
            fma2(acc[2 * q],     a.x, b2);
            fma2(acc[2 * q + 1], a.y, b2);
        }
    }

    float pm = THR * smn[mcol];
    int widx = (m0 + mwin) >> 5;
    #pragma unroll
    for (int p = 0; p < 8; p++) {
        F2U u; u.u = acc[p];
        unsigned w0 = __ballot_sync(0xffffffffu, u.f.x > pm * sn[ng + 2 * p]);
        unsigned w1 = __ballot_sync(0xffffffffu, u.f.y > pm * sn[ng + 2 * p + 1]);
        if (lane == 0) {
            int row0 = n0 + ng + 2 * p;
            g_adj[(b * 4096 + row0) * 128 + widx]     = w0;
            g_adj[(b * 4096 + row0 + 1) * 128 + widx] = w1;
            atomicAdd(&sdeg[ng + 2 * p],     __popc(w0));
            atomicAdd(&sdeg[ng + 2 * p + 1], __popc(w1));
        }
    }
    __syncthreads();
    if (t < 64) atomicAdd(&g_deg[b * 4096 + n0 + t], sdeg[t]);
}

// ---------------- diffusion + FC + instance-norm + relu (one layer) ------
// Block: 64 n-rows, all 64 channels, loops full m=4096 in 64-chunks.
// Coefficient tile built once per chunk as duplicated float2 (no PACK in
// inner loop). Warp: lane&15 -> c-quad, lane>>4 -> n-half; thread owns 4n x 4c.
__global__ void __launch_bounds__(256) k_layer(int layer,
                                               const float* __restrict__ W,
                                               float* __restrict__ out_final) {
    union SmemU {
        struct { float2 cf[64][64]; float xs[64][64]; } m;   // 32KB + 16KB
        struct { float lx[64][68]; float w[64][64]; } e;
    };
    __shared__ __align__(16) SmemU S;

    const float* xin = (layer == 0) ? g_xt : g_x1;
    float*       xout = (layer == 0) ? g_x1 : out_final;

    int b = blockIdx.y, n0 = blockIdx.x * 64;
    int t = threadIdx.x, warp = t >> 5, lane = t & 31;
    int cb = (lane & 15) * 4;
    int nh = lane >> 4;
    int nbase = warp * 8 + nh * 4;   // local n rows nbase..nbase+3

    ull acc[4][2];
    #pragma unroll
    for (int i = 0; i < 4; i++) { acc[i][0] = 0ULL; acc[i][1] = 0ULL; }

    const unsigned* adjb = g_adj + (b * 4096 + n0) * 128;
    const float* dvb = g_dinv + b * 4096;
    const float* xb  = xin + b * 4096 * 64;

    int ld_n = t >> 2, ld_q = t & 3;

    for (int mc = 0; mc < 64; mc++) {
        int m0 = mc * 64;
        __syncthreads();
        // stage x rows
        {
            const float4* g = (const float4*)(xb + (m0 + ld_n) * 64 + ld_q * 16);
            float4* s = (float4*)&S.m.xs[ld_n][ld_q * 16];
            #pragma unroll
            for (int j = 0; j < 4; j++) s[j] = g[j];
        }
        // build duplicated coefficient tile: cf[n][m] = {c,c}, c = bit ? dinv[m] : 0
        {
            unsigned w = adjb[ld_n * 128 + ((m0 + ld_q * 16) >> 5)];
            int sh = (ld_q * 16) & 31;
            const float4* dv4 = (const float4*)(dvb + m0 + ld_q * 16);
            float4* cfp = (float4*)&S.m.cf[ld_n][ld_q * 16];
            #pragma unroll
            for (int j = 0; j < 4; j++) {
                float4 d = dv4[j];
                float c0 = ((w >> (sh + 4 * j + 0)) & 1u) ? d.x : 0.f;
                float c1 = ((w >> (sh + 4 * j + 1)) & 1u) ? d.y : 0.f;
                float c2 = ((w >> (sh + 4 * j + 2)) & 1u) ? d.z : 0.f;
                float c3 = ((w >> (sh + 4 * j + 3)) & 1u) ? d.w : 0.f;
                cfp[2 * j]     = make_float4(c0, c0, c1, c1);
                cfp[2 * j + 1] = make_float4(c2, c2, c3, c3);
            }
        }
        __syncthreads();
        // dense FMA2 inner loop over the 64-m chunk
        #pragma unroll 4
        for (int ml = 0; ml < 64; ml++) {
            float4 xv = *(const float4*)&S.m.xs[ml][cb];
            F2U lo, hi;
            lo.f = make_float2(xv.x, xv.y);
            hi.f = make_float2(xv.z, xv.w);
            #pragma unroll
            for (int i = 0; i < 4; i++) {
                ull c2 = *(const ull*)&S.m.cf[nbase + i][ml];
                fma2(acc[i][0], c2, lo.u);
                fma2(acc[i][1], c2, hi.u);
            }
        }
    }
    __syncthreads();   // all reads of S.m done before reusing smem

    // scale by dinv_n, stage lx tile
    #pragma unroll
    for (int i = 0; i < 4; i++) {
        float dn = g_dinv[b * 4096 + n0 + nbase + i];
        F2U a0, a1; a0.u = acc[i][0]; a1.u = acc[i][1];
        float* lp = &S.e.lx[nbase + i][cb];
        lp[0] = a0.f.x * dn; lp[1] = a0.f.y * dn;
        lp[2] = a1.f.x * dn; lp[3] = a1.f.y * dn;
    }
    // stage W
    {
        const float4* g = (const float4*)(W + (t >> 2) * 64 + (t & 3) * 16);
        float4* s = (float4*)&S.e.w[t >> 2][(t & 3) * 16];
        #pragma unroll
        for (int j = 0; j < 4; j++) s[j] = g[j];
    }
    __syncthreads();

    // h = lx @ W, instance-norm over f (64), relu, write out.
    // thread: n = t>>2 (4 threads per row), f = (t&3)*16 + 0..15
    {
        int n = t >> 2, f0 = (t & 3) * 16;
        float h[16];
        #pragma unroll
        for (int j = 0; j < 16; j++) h[j] = 0.f;
        #pragma unroll 4
        for (int c = 0; c < 64; c++) {
            float a = S.e.lx[n][c];
            const float4* wr = (const float4*)&S.e.w[c][f0];
            #pragma unroll
            for (int q = 0; q < 4; q++) {
                float4 wv = wr[q];
                h[4 * q + 0] = fmaf(a, wv.x, h[4 * q + 0]);
                h[4 * q + 1] = fmaf(a, wv.y, h[4 * q + 1]);
                h[4 * q + 2] = fmaf(a, wv.z, h[4 * q + 2]);
                h[4 * q + 3] = fmaf(a, wv.w, h[4 * q + 3]);
            }
        }
        float s = 0.f;
        #pragma unroll
        for (int j = 0; j < 16; j++) s += h[j];
        s += __shfl_xor_sync(0xffffffffu, s, 1);
        s += __shfl_xor_sync(0xffffffffu, s, 2);
        float mean = s * (1.f / 64.f);
        float vq = 0.f;
        #pragma unroll
        for (int j = 0; j < 16; j++) { float d = h[j] - mean; vq += d * d; }
        vq += __shfl_xor_sync(0xffffffffu, vq, 1);
        vq += __shfl_xor_sync(0xffffffffu, vq, 2);
        float inv = 1.0f / sqrtf(vq * (1.f / 64.f) + EPSI);

        float4* op = (float4*)(xout + (b * 4096 + n0 + n) * 64 + f0);
        #pragma unroll
        for (int q = 0; q < 4; q++) {
            float4 o;
            o.x = fmaxf((h[4 * q + 0] - mean) * inv, 0.f);
            o.y = fmaxf((h[4 * q + 1] - mean) * inv, 0.f);
            o.z = fmaxf((h[4 * q + 2] - mean) * inv, 0.f);
            o.w = fmaxf((h[4 * q + 3] - mean) * inv, 0.f);
            op[q] = o;
        }
    }
}

// ---------------- launch ----------------
extern "C" void kernel_launch(void* const* d_in, const int* in_sizes, int n_in,
                              void* d_out, int out_size) {
    const float* x  = (const float*)d_in[0];
    const float* W0 = (const float*)d_in[1];
    const float* W1 = (const float*)d_in[2];
    float* out = (float*)d_out;

    k_zero_deg<<<64, 256>>>();
    k_transpose<<<dim3(128, 2, 4), dim3(32, 8)>>>(x);
    k_norm<<<64, 256>>>();
    k_gram<<<dim3(64, 64, 4), 256>>>(x);
    k_dinv<<<64, 256>>>();
    k_layer<<<dim3(64, 4), 256>>>(0, W0, nullptr);
    k_layer<<<dim3(64, 4), 256>>>(1, W1, out);
}

// round 3
// speedup vs baseline: 1.2284x; 1.2284x over previous
#include <cuda_runtime.h>
#include <math.h>

#define THR 0.005f
#define EPSI 1e-5f
#define NBATCH 4
#define NNODE 4096
#define NCH 64

typedef unsigned long long ull;

// ---------------- device scratch ----------------
__device__ __align__(16) float g_xt[NBATCH * NNODE * NCH];   // x transposed [b][n][c]
__device__ __align__(16) float g_x1[NBATCH * NNODE * NCH];   // layer-1 output
__device__ __align__(16) float g_lx[NBATCH * NNODE * NCH];   // diffusion output (scaled)
__device__ __align__(16) float g_snorm[NBATCH * NNODE];
__device__ __align__(16) float g_dinv[NBATCH * NNODE];
__device__ __align__(16) ull   g_dinv2[NBATCH * NNODE];      // duplicated {d,d}
__device__ __align__(16) unsigned g_adj[NBATCH * NNODE * 128];

// ---------------- packed fp32x2 helpers ----------------
__device__ __forceinline__ void fma2(ull& d, ull a, ull b) {
    asm("fma.rn.f32x2 %0, %1, %2, %0;" : "+l"(d) : "l"(a), "l"(b));
}
__device__ __forceinline__ ull pack2(float x) {
    ull r; asm("mov.b64 %0, {%1, %1};" : "=l"(r) : "f"(x)); return r;
}
union F2U { ull u; float2 f; };

// ---------------- transpose & norms ----------------
__global__ void k_transpose(const float* __restrict__ x) {
    __shared__ float t[32][33];
    int b = blockIdx.z, c0 = blockIdx.y * 32, n0 = blockIdx.x * 32;
    int tx = threadIdx.x, ty = threadIdx.y;
    const float* xp = x + ((b * 64 + c0) * NNODE) + n0;
    #pragma unroll
    for (int i = ty; i < 32; i += 8) t[i][tx] = xp[i * NNODE + tx];
    __syncthreads();
    float* op = g_xt + ((b * NNODE + n0) * 64) + c0;
    #pragma unroll
    for (int i = ty; i < 32; i += 8) op[i * 64 + tx] = t[tx][i];
}

__global__ void k_norm() {
    int i = blockIdx.x * 256 + threadIdx.x;
    if (i >= NBATCH * NNODE) return;
    const float4* p = (const float4*)(g_xt + (size_t)i * 64);
    float s = 0.f;
    #pragma unroll
    for (int j = 0; j < 16; j++) {
        float4 v = p[j];
        s += v.x * v.x + v.y * v.y + v.z * v.z + v.w * v.w;
    }
    g_snorm[i] = sqrtf(s);
}

// ---------------- Gram + threshold -> adjacency bits ----------------
// Block: 128n x 128m tile, K=64 in two 32-chunks. 256 threads, 8 warps.
// Warp tile 32n x 64m; lane: r=lane>>3 (n-sub), c3=lane&7 (m-sub).
// Thread tile: 8 n-rows (nb..nb+7) x 8 m: {mb..mb+3, mb+32..mb+35}.
// All smem reads conflict-free; bits packed via shfl-OR of nibbles.
__global__ void __launch_bounds__(256, 2) k_gram(const float* __restrict__ x) {
    __shared__ __align__(16) float As[32][128];
    __shared__ __align__(16) float Bs[32][128];
    __shared__ float sns[128], pms[128];

    int b = blockIdx.z;
    int n0 = blockIdx.y * 128, m0 = blockIdx.x * 128;
    int t = threadIdx.x;

    if (t < 128) sns[t] = g_snorm[b * NNODE + n0 + t];
    else         pms[t - 128] = THR * g_snorm[b * NNODE + m0 + (t - 128)];

    int warp = t >> 5, lane = t & 31;
    int r = lane >> 3, c3 = lane & 7;
    int nb = (warp >> 1) * 32 + r * 8;
    int mwarp = (warp & 1) * 64;
    int mb = mwarp + c3 * 4;

    ull acc[8][4];
    #pragma unroll
    for (int i = 0; i < 8; i++)
        #pragma unroll
        for (int p = 0; p < 4; p++) acc[i][p] = 0ULL;

    const float* xa = x + (size_t)(b * 64) * NNODE;

    for (int kc = 0; kc < 2; kc++) {
        __syncthreads();
        #pragma unroll
        for (int i = 0; i < 4; i++) {
            int f4 = t + i * 256;                 // 0..1023 float4 slots
            int row = f4 >> 5, c4 = f4 & 31;
            const float* src = xa + (size_t)(kc * 32 + row) * NNODE;
            *(float4*)&As[row][c4 * 4] = *(const float4*)(src + n0 + c4 * 4);
            *(float4*)&Bs[row][c4 * 4] = *(const float4*)(src + m0 + c4 * 4);
        }
        __syncthreads();
        #pragma unroll 8
        for (int k = 0; k < 32; k++) {
            float4 a0 = *(const float4*)&As[k][nb];
            float4 a1 = *(const float4*)&As[k][nb + 4];
            ulonglong2 b0 = *(const ulonglong2*)&Bs[k][mb];
            ulonglong2 b1 = *(const ulonglong2*)&Bs[k][mb + 32];
            float av[8] = {a0.x, a0.y, a0.z, a0.w, a1.x, a1.y, a1.z, a1.w};
            #pragma unroll
            for (int i = 0; i < 8; i++) {
                ull a2 = pack2(av[i]);
                fma2(acc[i][0], a2, b0.x);
                fma2(acc[i][1], a2, b0.y);
                fma2(acc[i][2], a2, b1.x);
                fma2(acc[i][3], a2, b1.y);
            }
        }
    }

    // ---- threshold + bit packing ----
    float pmv[8];
    #pragma unroll
    for (int j = 0; j < 4; j++) {
        pmv[j]     = pms[mwarp + c3 * 4 + j];
        pmv[4 + j] = pms[mwarp + 32 + c3 * 4 + j];
    }
    int bw = (m0 + mwarp) >> 5;
    #pragma unroll
    for (int i = 0; i < 8; i++) {
        float sni = sns[nb + i];
        F2U q0, q1, q2, q3;
        q0.u = acc[i][0]; q1.u = acc[i][1]; q2.u = acc[i][2]; q3.u = acc[i][3];
        unsigned nib0 = (q0.f.x > sni * pmv[0] ? 1u : 0u) | (q0.f.y > sni * pmv[1] ? 2u : 0u)
                      | (q1.f.x > sni * pmv[2] ? 4u : 0u) | (q1.f.y > sni * pmv[3] ? 8u : 0u);
        unsigned nib1 = (q2.f.x > sni * pmv[4] ? 1u : 0u) | (q2.f.y > sni * pmv[5] ? 2u : 0u)
                      | (q3.f.x > sni * pmv[6] ? 4u : 0u) | (q3.f.y > sni * pmv[7] ? 8u : 0u);
        unsigned v0 = nib0 << (c3 * 4);
        unsigned v1 = nib1 << (c3 * 4);
        #pragma unroll
        for (int s = 1; s <= 4; s <<= 1) {
            v0 |= __shfl_xor_sync(0xffffffffu, v0, s);
            v1 |= __shfl_xor_sync(0xffffffffu, v1, s);
        }
        if (c3 == 0) {
            size_t gr = (size_t)(b * NNODE + n0 + nb + i) * 128;
            g_adj[gr + bw]     = v0;
            g_adj[gr + bw + 1] = v1;
        }
    }
}

// ---------------- degree from popc ----------------
__global__ void k_deg() {
    int row = blockIdx.x * 8 + (threadIdx.x >> 5);
    int lane = threadIdx.x & 31;
    const uint4* a = (const uint4*)(g_adj + (size_t)row * 128);
    uint4 v = a[lane];
    int c = __popc(v.x) + __popc(v.y) + __popc(v.z) + __popc(v.w);
    #pragma unroll
    for (int s = 16; s; s >>= 1) c += __shfl_xor_sync(0xffffffffu, c, s);
    if (lane == 0) {
        float d = 1.0f / sqrtf((float)c);
        g_dinv[row]  = d;
        g_dinv2[row] = pack2(d);
    }
}

// ---------------- diffusion: lx = D^-1/2 A D^-1/2 @ x -> g_lx ----------------
// Block 128n x 64c (full C), 512 threads (16 warps). Thread tile 2n x 8c.
// m-loop in 32-chunks; coef tile cf2[m][n] pre-duplicated ull built from
// adjacency bits; x-tile and adj word register-prefetched one chunk ahead.
__global__ void __launch_bounds__(512) k_diff(int layer) {
    __shared__ __align__(16) ull   cf2[32][128];   // 32KB
    __shared__ __align__(16) float xs[32][64];     // 8KB

    const float* xin = (layer == 0) ? g_xt : g_x1;

    int b = blockIdx.y, n0 = blockIdx.x * 128;
    int t = threadIdx.x;
    int w = t >> 5, la = (t >> 3) & 3, ln = t & 7;
    int nl = w * 8 + la * 2;

    const float* xb = xin + (size_t)b * NNODE * NCH;
    const unsigned* adjrow = g_adj + (size_t)(b * NNODE + n0 + t) * 128; // used t<128
    const ull* dv2 = g_dinv2 + b * NNODE;

    ull acc[2][4];
    #pragma unroll
    for (int i = 0; i < 2; i++)
        #pragma unroll
        for (int p = 0; p < 4; p++) acc[i][p] = 0ULL;

    // prefetch chunk 0
    unsigned wadj = 0;
    float4 xf0, xf1;
    int tt = t - 128;
    if (t < 128) {
        wadj = adjrow[0];
    } else if (t < 384) {
        xf0 = *(const float4*)(xb + (size_t)(tt >> 4) * NCH + (tt & 15) * 4);
        xf1 = *(const float4*)(xb + (size_t)(16 + (tt >> 4)) * NCH + (tt & 15) * 4);
    }

    for (int ch = 0; ch < 128; ch++) {
        __syncthreads();   // previous chunk's reads complete
        if (t < 128) {
            unsigned wv = wadj;
            const ull* dvc = dv2 + ch * 32;
            #pragma unroll
            for (int m = 0; m < 32; m++) {
                ull d = dvc[m];
                cf2[m][t] = ((wv >> m) & 1u) ? d : 0ULL;
            }
            if (ch + 1 < 128) wadj = adjrow[ch + 1];
        } else if (t < 384) {
            *(float4*)&xs[tt >> 4][(tt & 15) * 4]        = xf0;
            *(float4*)&xs[16 + (tt >> 4)][(tt & 15) * 4] = xf1;
            if (ch + 1 < 128) {
                int mrow = (ch + 1) * 32;
                xf0 = *(const float4*)(xb + (size_t)(mrow + (tt >> 4)) * NCH + (tt & 15) * 4);
                xf1 = *(const float4*)(xb + (size_t)(mrow + 16 + (tt >> 4)) * NCH + (tt & 15) * 4);
            }
        }
        __syncthreads();
        #pragma unroll 8
        for (int m = 0; m < 32; m++) {
            ulonglong2 cf = *(const ulonglong2*)&cf2[m][nl];
            ulonglong2 x0 = *(const ulonglong2*)&xs[m][ln * 4];
            ulonglong2 x1 = *(const ulonglong2*)&xs[m][ln * 4 + 32];
            fma2(acc[0][0], cf.x, x0.x); fma2(acc[0][1], cf.x, x0.y);
            fma2(acc[0][2], cf.x, x1.x); fma2(acc[0][3], cf.x, x1.y);
            fma2(acc[1][0], cf.y, x0.x); fma2(acc[1][1], cf.y, x0.y);
            fma2(acc[1][2], cf.y, x1.x); fma2(acc[1][3], cf.y, x1.y);
        }
    }

    #pragma unroll
    for (int i = 0; i < 2; i++) {
        int gn = b * NNODE + n0 + nl + i;
        float dn = g_dinv[gn];
        F2U p0, p1, p2, p3;
        p0.u = acc[i][0]; p1.u = acc[i][1]; p2.u = acc[i][2]; p3.u = acc[i][3];
        float4 o0 = make_float4(p0.f.x * dn, p0.f.y * dn, p1.f.x * dn, p1.f.y * dn);
        float4 o1 = make_float4(p2.f.x * dn, p2.f.y * dn, p3.f.x * dn, p3.f.y * dn);
        *(float4*)(g_lx + (size_t)gn * NCH + ln * 4)      = o0;
        *(float4*)(g_lx + (size_t)gn * NCH + ln * 4 + 32) = o1;
    }
}

// ---------------- FC + instance-norm + relu ----------------
// Block: 64 rows, 256 threads = 4 threads/row (16 f each).
__global__ void __launch_bounds__(256) k_fc(const float* __restrict__ W,
                                            float* __restrict__ out_final,
                                            int layer) {
    __shared__ __align__(16) float lxs[64][72];
    __shared__ __align__(16) float ws[64][64];

    float* xout = (layer == 0) ? g_x1 : out_final;

    int b = blockIdx.y, n0 = blockIdx.x * 64;
    int t = threadIdx.x;
    int n = t >> 2, f0 = (t & 3) * 16;

    {
        const float4* g = (const float4*)(g_lx + (size_t)(b * NNODE + n0 + (t >> 2)) * NCH + (t & 3) * 16);
        float4* s = (float4*)&lxs[t >> 2][(t & 3) * 16];
        #pragma unroll
        for (int j = 0; j < 4; j++) s[j] = g[j];
        const float4* gw = (const float4*)(W + (t >> 2) * 64 + (t & 3) * 16);
        float4* sw = (float4*)&ws[t >> 2][(t & 3) * 16];
        #pragma unroll
        for (int j = 0; j < 4; j++) sw[j] = gw[j];
    }
    __syncthreads();

    ull h[8];
    #pragma unroll
    for (int j = 0; j < 8; j++) h[j] = 0ULL;
    #pragma unroll 8
    for (int c = 0; c < 64; c++) {
        ull a2 = pack2(lxs[n][c]);
        ulonglong2 w0 = *(const ulonglong2*)&ws[c][f0];
        ulonglong2 w1 = *(const ulonglong2*)&ws[c][f0 + 4];
        ulonglong2 w2 = *(const ulonglong2*)&ws[c][f0 + 8];
        ulonglong2 w3 = *(const ulonglong2*)&ws[c][f0 + 12];
        fma2(h[0], a2, w0.x); fma2(h[1], a2, w0.y);
        fma2(h[2], a2, w1.x); fma2(h[3], a2, w1.y);
        fma2(h[4], a2, w2.x); fma2(h[5], a2, w2.y);
        fma2(h[6], a2, w3.x); fma2(h[7], a2, w3.y);
    }
    float hv[16];
    #pragma unroll
    for (int j = 0; j < 8; j++) { F2U u; u.u = h[j]; hv[2 * j] = u.f.x; hv[2 * j + 1] = u.f.y; }

    float s = 0.f;
    #pragma unroll
    for (int j = 0; j < 16; j++) s += hv[j];
    s += __shfl_xor_sync(0xffffffffu, s, 1);
    s += __shfl_xor_sync(0xffffffffu, s, 2);
    float mean = s * (1.f / 64.f);
    float vq = 0.f;
    #pragma unroll
    for (int j = 0; j < 16; j++) { float d = hv[j] - mean; vq += d * d; }
    vq += __shfl_xor_sync(0xffffffffu, vq, 1);
    vq += __shfl_xor_sync(0xffffffffu, vq, 2);
    float inv = 1.0f / sqrtf(vq * (1.f / 64.f) + EPSI);

    float4* op = (float4*)(xout + (size_t)(b * NNODE + n0 + n) * 64 + f0);
    #pragma unroll
    for (int q = 0; q < 4; q++) {
        float4 o;
        o.x = fmaxf((hv[4 * q + 0] - mean) * inv, 0.f);
        o.y = fmaxf((hv[4 * q + 1] - mean) * inv, 0.f);
        o.z = fmaxf((hv[4 * q + 2] - mean) * inv, 0.f);
        o.w = fmaxf((hv[4 * q + 3] - mean) * inv, 0.f);
        op[q] = o;
    }
}

// ---------------- launch ----------------
extern "C" void kernel_launch(void* const* d_in, const int* in_sizes, int n_in,
                              void* d_out, int out_size) {
    const float* x  = (const float*)d_in[0];
    const float* W0 = (const float*)d_in[1];
    const float* W1 = (const float*)d_in[2];
    float* out = (float*)d_out;

    k_transpose<<<dim3(128, 2, 4), dim3(32, 8)>>>(x);
    k_norm<<<64, 256>>>();
    k_gram<<<dim3(32, 32, 4), 256>>>(x);
    k_deg<<<2048, 256>>>();
    k_diff<<<dim3(32, 4), 512>>>(0);
    k_fc<<<dim3(64, 4), 256>>>(W0, out, 0);
    k_diff<<<dim3(32, 4), 512>>>(1);
    k_fc<<<dim3(64, 4), 256>>>(W1, out, 1);
}

// round 4
// speedup vs baseline: 1.6258x; 1.3235x over previous
#include <cuda_runtime.h>
#include <math.h>

#define THR 0.005f
#define EPSI 1e-5f
#define NBATCH 4
#define NNODE 4096
#define NCH 64

typedef unsigned long long ull;

// ---------------- device scratch ----------------
__device__ __align__(16) float g_xt[NBATCH * NNODE * NCH];    // x transposed [b][n][c]
__device__ __align__(16) float g_x1[NBATCH * NNODE * NCH];    // layer-1 output
__device__ __align__(16) float g_xd[NBATCH * NNODE * NCH];    // dinv_m-prescaled input
__device__ __align__(16) float g_lxp[4ULL * NBATCH * NNODE * NCH]; // diffusion partials [ms][b][n][c]
__device__ __align__(16) float g_snorm[NBATCH * NNODE];
__device__ __align__(16) float g_dinv[NBATCH * NNODE];
__device__ __align__(16) unsigned g_adjT[NBATCH * 128 * NNODE]; // adjacency bits [b][word][n]

// ---------------- packed fp32x2 helpers ----------------
__device__ __forceinline__ void fma2(ull& d, ull a, ull b) {
    asm("fma.rn.f32x2 %0, %1, %2, %0;" : "+l"(d) : "l"(a), "l"(b));
}
__device__ __forceinline__ ull pack2(float x) {
    ull r; asm("mov.b64 %0, {%1, %1};" : "=l"(r) : "f"(x)); return r;
}
// predicated row-accumulate: if (bit) d[j] += a_j  (4x fadd2 under one setp)
__device__ __forceinline__ void prow(ull* d, ull a0, ull a1, ull a2, ull a3, unsigned bit) {
    asm("{\n\t.reg .pred p;\n\t"
        "setp.ne.u32 p, %8, 0;\n\t"
        "@p add.rn.f32x2 %0, %0, %4;\n\t"
        "@p add.rn.f32x2 %1, %1, %5;\n\t"
        "@p add.rn.f32x2 %2, %2, %6;\n\t"
        "@p add.rn.f32x2 %3, %3, %7;\n\t}"
        : "+l"(d[0]), "+l"(d[1]), "+l"(d[2]), "+l"(d[3])
        : "l"(a0), "l"(a1), "l"(a2), "l"(a3), "r"(bit));
}
union F2U { ull u; float2 f; };

// ---------------- transpose & norms ----------------
__global__ void k_transpose(const float* __restrict__ x) {
    __shared__ float t[32][33];
    int b = blockIdx.z, c0 = blockIdx.y * 32, n0 = blockIdx.x * 32;
    int tx = threadIdx.x, ty = threadIdx.y;
    const float* xp = x + ((b * 64 + c0) * NNODE) + n0;
    #pragma unroll
    for (int i = ty; i < 32; i += 8) t[i][tx] = xp[i * NNODE + tx];
    __syncthreads();
    float* op = g_xt + ((b * NNODE + n0) * 64) + c0;
    #pragma unroll
    for (int i = ty; i < 32; i += 8) op[i * 64 + tx] = t[tx][i];
}

__global__ void k_norm() {
    int i = blockIdx.x * 256 + threadIdx.x;
    if (i >= NBATCH * NNODE) return;
    const float4* p = (const float4*)(g_xt + (size_t)i * 64);
    float s = 0.f;
    #pragma unroll
    for (int j = 0; j < 16; j++) {
        float4 v = p[j];
        s += v.x * v.x + v.y * v.y + v.z * v.z + v.w * v.w;
    }
    g_snorm[i] = sqrtf(s);
}

// ---------------- Gram + threshold -> adjacency bits (triangular) --------
// Only upper-triangular 128x128 block pairs (i<=j); writes BOTH orientations
// into the transposed adjacency layout [b][word][n].
__global__ void __launch_bounds__(256, 2) k_gram(const float* __restrict__ x) {
    __shared__ __align__(16) float As[32][128];
    __shared__ __align__(16) float Bs[32][128];
    __shared__ float sns[128], pms[128];

    int b = blockIdx.z;
    // decode triangular pair (bi <= bj) from blockIdx.x in [0,528)
    int xid = blockIdx.x;
    int bj = (int)((sqrtf(8.f * xid + 1.f) - 1.f) * 0.5f);
    while ((bj + 1) * (bj + 2) / 2 <= xid) bj++;
    while (bj * (bj + 1) / 2 > xid) bj--;
    int bi = xid - bj * (bj + 1) / 2;
    int n0 = bi * 128, m0 = bj * 128;

    int t = threadIdx.x;
    if (t < 128) sns[t] = g_snorm[b * NNODE + n0 + t];
    else         pms[t - 128] = THR * g_snorm[b * NNODE + m0 + (t - 128)];

    int warp = t >> 5, lane = t & 31;
    int r = lane >> 3, c3 = lane & 7;
    int warpn = (warp >> 1) * 32;
    int nb = warpn + r * 8;
    int mwarp = (warp & 1) * 64;
    int mb = mwarp + c3 * 4;

    ull acc[8][4];
    #pragma unroll
    for (int i = 0; i < 8; i++)
        #pragma unroll
        for (int p = 0; p < 4; p++) acc[i][p] = 0ULL;

    const float* xa = x + (size_t)(b * 64) * NNODE;

    for (int kc = 0; kc < 2; kc++) {
        __syncthreads();
        #pragma unroll
        for (int i = 0; i < 4; i++) {
            int f4 = t + i * 256;
            int row = f4 >> 5, c4 = f4 & 31;
            const float* src = xa + (size_t)(kc * 32 + row) * NNODE;
            *(float4*)&As[row][c4 * 4] = *(const float4*)(src + n0 + c4 * 4);
            *(float4*)&Bs[row][c4 * 4] = *(const float4*)(src + m0 + c4 * 4);
        }
        __syncthreads();
        #pragma unroll 8
        for (int k = 0; k < 32; k++) {
            float4 a0 = *(const float4*)&As[k][nb];
            float4 a1 = *(const float4*)&As[k][nb + 4];
            ulonglong2 b0 = *(const ulonglong2*)&Bs[k][mb];
            ulonglong2 b1 = *(const ulonglong2*)&Bs[k][mb + 32];
            float av[8] = {a0.x, a0.y, a0.z, a0.w, a1.x, a1.y, a1.z, a1.w};
            #pragma unroll
            for (int i = 0; i < 8; i++) {
                ull a2 = pack2(av[i]);
                fma2(acc[i][0], a2, b0.x);
                fma2(acc[i][1], a2, b0.y);
                fma2(acc[i][2], a2, b1.x);
                fma2(acc[i][3], a2, b1.y);
            }
        }
    }

    // ---- threshold + both-orientation bit packing ----
    float pmv[8];
    #pragma unroll
    for (int j = 0; j < 4; j++) {
        pmv[j]     = pms[mwarp + c3 * 4 + j];
        pmv[4 + j] = pms[mwarp + 32 + c3 * 4 + j];
    }
    unsigned bytesT[8];
    #pragma unroll
    for (int j = 0; j < 8; j++) bytesT[j] = 0u;

    int bw = (m0 + mwarp) >> 5;          // m-word base (normal orientation)
    int nw = (n0 + warpn) >> 5;          // n-word (transposed orientation)

    #pragma unroll
    for (int i = 0; i < 8; i++) {
        float sni = sns[nb + i];
        F2U q0, q1, q2, q3;
        q0.u = acc[i][0]; q1.u = acc[i][1]; q2.u = acc[i][2]; q3.u = acc[i][3];
        unsigned c0 = q0.f.x > sni * pmv[0];
        unsigned c1 = q0.f.y > sni * pmv[1];
        unsigned c2 = q1.f.x > sni * pmv[2];
        unsigned c3b = q1.f.y > sni * pmv[3];
        unsigned c4 = q2.f.x > sni * pmv[4];
        unsigned c5 = q2.f.y > sni * pmv[5];
        unsigned c6 = q3.f.x > sni * pmv[6];
        unsigned c7 = q3.f.y > sni * pmv[7];
        unsigned v0 = (c0 | (c1 << 1) | (c2 << 2) | (c3b << 3)) << (c3 * 4);
        unsigned v1 = (c4 | (c5 << 1) | (c6 << 2) | (c7 << 3)) << (c3 * 4);
        bytesT[0] |= c0 << i;  bytesT[1] |= c1 << i;
        bytesT[2] |= c2 << i;  bytesT[3] |= c3b << i;
        bytesT[4] |= c4 << i;  bytesT[5] |= c5 << i;
        bytesT[6] |= c6 << i;  bytesT[7] |= c7 << i;
        #pragma unroll
        for (int s = 1; s <= 4; s <<= 1) {
            v0 |= __shfl_xor_sync(0xffffffffu, v0, s);
            v1 |= __shfl_xor_sync(0xffffffffu, v1, s);
        }
        if (c3 == 0) {
            int gn = n0 + nb + i;
            g_adjT[((size_t)b * 128 + bw)     * NNODE + gn] = v0;
            g_adjT[((size_t)b * 128 + bw + 1) * NNODE + gn] = v1;
        }
    }
    // transposed orientation: bits over n (this warp's 32 n), rows = m
    #pragma unroll
    for (int jj = 0; jj < 8; jj++) {
        unsigned v = bytesT[jj] << (r * 8);
        v |= __shfl_xor_sync(0xffffffffu, v, 8);
        v |= __shfl_xor_sync(0xffffffffu, v, 16);
        if (r == 0) {
            int mg = m0 + mwarp + ((jj < 4) ? (c3 * 4 + jj) : (32 + c3 * 4 + jj - 4));
            g_adjT[((size_t)b * 128 + nw) * NNODE + mg] = v;
        }
    }
}

// ---------------- degree -> dinv ----------------
__global__ void k_deg() {
    int i = blockIdx.x * 256 + threadIdx.x;     // over B*N
    int b = i >> 12, nl = i & 4095;
    const unsigned* p = g_adjT + (size_t)b * 128 * NNODE + nl;
    int c = 0;
    #pragma unroll 8
    for (int w = 0; w < 128; w++) c += __popc(p[(size_t)w * NNODE]);
    g_dinv[i] = 1.0f / sqrtf((float)c);
}

// ---------------- prescale: xd = xin * dinv_m ----------------
__global__ void k_scale(int layer) {
    int i = blockIdx.x * 256 + threadIdx.x;     // float4 index, 262144 total
    const float4* xin = (const float4*)((layer == 0) ? g_xt : g_x1);
    float d = g_dinv[i >> 4];
    float4 v = xin[i];
    v.x *= d; v.y *= d; v.z *= d; v.w *= d;
    ((float4*)g_xd)[i] = v;
}

// ---------------- diffusion: partial lx over an m-quarter ----------------
// Block: 128 threads, tile 8n x 8c -> block covers 128 n x 64 c x 1024 m.
// Grid (32 nblk, 4 msplit, 4 b). Predicated FADD2 on adjacency bits.
__global__ void __launch_bounds__(128) k_diff() {
    __shared__ __align__(16) float xs[32][64];   // 8KB staging

    int b = blockIdx.z, ms = blockIdx.y, n0 = blockIdx.x * 128;
    int t = threadIdx.x;
    int tn = t >> 3, tc = t & 7;                 // 16 n-groups x 8 c-cols

    const float* xd = g_xd + (size_t)b * NNODE * NCH;
    const unsigned* adjp = g_adjT + ((size_t)b * 128 + ms * 32) * NNODE + n0 + tn * 8;

    ull acc[8][4];
    #pragma unroll
    for (int i = 0; i < 8; i++)
        #pragma unroll
        for (int p = 0; p < 4; p++) acc[i][p] = 0ULL;

    // prefetch chunk 0
    uint4 wv0 = *(const uint4*)(adjp);
    uint4 wv1 = *(const uint4*)(adjp + 4);
    float4 xf[4];
    #pragma unroll
    for (int k = 0; k < 4; k++) {
        int f = t + k * 128;                     // float4 slot 0..511
        xf[k] = *(const float4*)(xd + (size_t)(ms * 1024 + (f >> 4)) * NCH + (f & 15) * 4);
    }

    for (int ch = 0; ch < 32; ch++) {
        __syncthreads();
        #pragma unroll
        for (int k = 0; k < 4; k++) {
            int f = t + k * 128;
            *(float4*)&xs[f >> 4][(f & 15) * 4] = xf[k];
        }
        unsigned w0 = wv0.x, w1 = wv0.y, w2 = wv0.z, w3 = wv0.w;
        unsigned w4 = wv1.x, w5 = wv1.y, w6 = wv1.z, w7 = wv1.w;
        __syncthreads();
        if (ch + 1 < 32) {
            wv0 = *(const uint4*)(adjp + (size_t)(ch + 1) * NNODE);
            wv1 = *(const uint4*)(adjp + (size_t)(ch + 1) * NNODE + 4);
            #pragma unroll
            for (int k = 0; k < 4; k++) {
                int f = t + k * 128;
                xf[k] = *(const float4*)(xd + (size_t)(ms * 1024 + (ch + 1) * 32 + (f >> 4)) * NCH + (f & 15) * 4);
            }
        }
        #pragma unroll 8
        for (int m = 0; m < 32; m++) {
            ulonglong2 xa = *(const ulonglong2*)&xs[m][tc * 8];
            ulonglong2 xb = *(const ulonglong2*)&xs[m][tc * 8 + 4];
            prow(acc[0], xa.x, xa.y, xb.x, xb.y, (w0 >> m) & 1u);
            prow(acc[1], xa.x, xa.y, xb.x, xb.y, (w1 >> m) & 1u);
            prow(acc[2], xa.x, xa.y, xb.x, xb.y, (w2 >> m) & 1u);
            prow(acc[3], xa.x, xa.y, xb.x, xb.y, (w3 >> m) & 1u);
            prow(acc[4], xa.x, xa.y, xb.x, xb.y, (w4 >> m) & 1u);
            prow(acc[5], xa.x, xa.y, xb.x, xb.y, (w5 >> m) & 1u);
            prow(acc[6], xa.x, xa.y, xb.x, xb.y, (w6 >> m) & 1u);
            prow(acc[7], xa.x, xa.y, xb.x, xb.y, (w7 >> m) & 1u);
        }
    }

    // epilogue: scale by dinv_n, write partial slice
    float* lp = g_lxp + (size_t)ms * (NBATCH * NNODE * NCH);
    #pragma unroll
    for (int i = 0; i < 8; i++) {
        int gn = b * NNODE + n0 + tn * 8 + i;
        float dn = g_dinv[gn];
        F2U p0, p1, p2, p3;
        p0.u = acc[i][0]; p1.u = acc[i][1]; p2.u = acc[i][2]; p3.u = acc[i][3];
        float4 o0 = make_float4(p0.f.x * dn, p0.f.y * dn, p1.f.x * dn, p1.f.y * dn);
        float4 o1 = make_float4(p2.f.x * dn, p2.f.y * dn, p3.f.x * dn, p3.f.y * dn);
        *(float4*)(lp + (size_t)gn * NCH + tc * 8)     = o0;
        *(float4*)(lp + (size_t)gn * NCH + tc * 8 + 4) = o1;
    }
}

// ---------------- FC + instance-norm + relu ----------------
__global__ void __launch_bounds__(256) k_fc(const float* __restrict__ W,
                                            float* __restrict__ out_final,
                                            int layer) {
    __shared__ __align__(16) float lxs[64][72];
    __shared__ __align__(16) float ws[64][64];

    float* xout = (layer == 0) ? g_x1 : out_final;

    int b = blockIdx.y, n0 = blockIdx.x * 64;
    int t = threadIdx.x;
    int n = t >> 2, f0 = (t & 3) * 16;
    const size_t SL = (size_t)NBATCH * NNODE * NCH;

    {
        size_t base = ((size_t)(b * NNODE + n0 + (t >> 2))) * NCH + (t & 3) * 16;
        #pragma unroll
        for (int j = 0; j < 4; j++) {
            float4 v = *(const float4*)(g_lxp + base + j * 4);
            #pragma unroll
            for (int msl = 1; msl < 4; msl++) {
                float4 w2 = *(const float4*)(g_lxp + msl * SL + base + j * 4);
                v.x += w2.x; v.y += w2.y; v.z += w2.z; v.w += w2.w;
            }
            *(float4*)&lxs[t >> 2][(t & 3) * 16 + j * 4] = v;
        }
        const float4* gw = (const float4*)(W + (t >> 2) * 64 + (t & 3) * 16);
        float4* sw = (float4*)&ws[t >> 2][(t & 3) * 16];
        #pragma unroll
        for (int j = 0; j < 4; j++) sw[j] = gw[j];
    }
    __syncthreads();

    ull h[8];
    #pragma unroll
    for (int j = 0; j < 8; j++) h[j] = 0ULL;
    #pragma unroll 8
    for (int c = 0; c < 64; c++) {
        ull a2 = pack2(lxs[n][c]);
        ulonglong2 w0 = *(const ulonglong2*)&ws[c][f0];
        ulonglong2 w1 = *(const ulonglong2*)&ws[c][f0 + 4];
        ulonglong2 w2 = *(const ulonglong2*)&ws[c][f0 + 8];
        ulonglong2 w3 = *(const ulonglong2*)&ws[c][f0 + 12];
        fma2(h[0], a2, w0.x); fma2(h[1], a2, w0.y);
        fma2(h[2], a2, w1.x); fma2(h[3], a2, w1.y);
        fma2(h[4], a2, w2.x); fma2(h[5], a2, w2.y);
        fma2(h[6], a2, w3.x); fma2(h[7], a2, w3.y);
    }
    float hv[16];
    #pragma unroll
    for (int j = 0; j < 8; j++) { F2U u; u.u = h[j]; hv[2 * j] = u.f.x; hv[2 * j + 1] = u.f.y; }

    float s = 0.f;
    #pragma unroll
    for (int j = 0; j < 16; j++) s += hv[j];
    s += __shfl_xor_sync(0xffffffffu, s, 1);
    s += __shfl_xor_sync(0xffffffffu, s, 2);
    float mean = s * (1.f / 64.f);
    float vq = 0.f;
    #pragma unroll
    for (int j = 0; j < 16; j++) { float d = hv[j] - mean; vq += d * d; }
    vq += __shfl_xor_sync(0xffffffffu, vq, 1);
    vq += __shfl_xor_sync(0xffffffffu, vq, 2);
    float inv = 1.0f / sqrtf(vq * (1.f / 64.f) + EPSI);

    float4* op = (float4*)(xout + (size_t)(b * NNODE + n0 + n) * 64 + f0);
    #pragma unroll
    for (int q = 0; q < 4; q++) {
        float4 o;
        o.x = fmaxf((hv[4 * q + 0] - mean) * inv, 0.f);
        o.y = fmaxf((hv[4 * q + 1] - mean) * inv, 0.f);
        o.z = fmaxf((hv[4 * q + 2] - mean) * inv, 0.f);
        o.w = fmaxf((hv[4 * q + 3] - mean) * inv, 0.f);
        op[q] = o;
    }
}

// ---------------- launch ----------------
extern "C" void kernel_launch(void* const* d_in, const int* in_sizes, int n_in,
                              void* d_out, int out_size) {
    const float* x  = (const float*)d_in[0];
    const float* W0 = (const float*)d_in[1];
    const float* W1 = (const float*)d_in[2];
    float* out = (float*)d_out;

    k_transpose<<<dim3(128, 2, 4), dim3(32, 8)>>>(x);
    k_norm<<<64, 256>>>();
    k_gram<<<dim3(528, 1, 4), 256>>>(x);
    k_deg<<<64, 256>>>();
    k_scale<<<1024, 256>>>(0);
    k_diff<<<dim3(32, 4, 4), 128>>>();
    k_fc<<<dim3(64, 4), 256>>>(W0, nullptr, 0);
    k_scale<<<1024, 256>>>(1);
    k_diff<<<dim3(32, 4, 4), 128>>>();
    k_fc<<<dim3(64, 4), 256>>>(W1, out, 1);
}

// round 5
// speedup vs baseline: 4.9112x; 3.0208x over previous
#include <cuda_runtime.h>
#include <cuda_bf16.h>
#include <math.h>

#define THR 0.005f
#define EPSI 1e-5f
#define NBATCH 4
#define NNODE 4096
#define NCH 64
#define SP 136   // padded bf16 row stride for B smem tile (272B, conflict-free)

typedef unsigned long long ull;
typedef unsigned int uint;

// ---------------- device scratch ----------------
__device__ __align__(16) float g_xt[NBATCH * NNODE * NCH];     // x transposed [b][n][c]
__device__ __align__(16) float g_x1[NBATCH * NNODE * NCH];     // layer-1 output
__device__ __align__(16) float g_lx[NBATCH * NNODE * NCH];     // diffusion output
__device__ __align__(16) float g_snorm[NBATCH * NNODE];
__device__ __align__(16) float g_dinv[NBATCH * NNODE];
__device__ __align__(16) unsigned g_adjT[NBATCH * 128 * NNODE];        // bits [b][word_m][n]
__device__ __align__(16) unsigned short g_xs[NBATCH * NNODE * 128];    // bf16 split [b][m][hi64|lo64]

// ---------------- packed fp32x2 helpers (gram/fc) ----------------
__device__ __forceinline__ void fma2(ull& d, ull a, ull b) {
    asm("fma.rn.f32x2 %0, %1, %2, %0;" : "+l"(d) : "l"(a), "l"(b));
}
__device__ __forceinline__ ull pack2(float x) {
    ull r; asm("mov.b64 %0, {%1, %1};" : "=l"(r) : "f"(x)); return r;
}
union F2U { ull u; float2 f; };

// bit-pair -> packed bf16x2 {1.0/0.0, 1.0/0.0}
__device__ __forceinline__ uint bfpair(uint u) {
    return ((u & 1u) ? 0x3F80u : 0u) | ((u & 2u) ? 0x3F800000u : 0u);
}

// ---------------- transpose & norms ----------------
__global__ void k_transpose(const float* __restrict__ x) {
    __shared__ float t[32][33];
    int b = blockIdx.z, c0 = blockIdx.y * 32, n0 = blockIdx.x * 32;
    int tx = threadIdx.x, ty = threadIdx.y;
    const float* xp = x + ((b * 64 + c0) * NNODE) + n0;
    #pragma unroll
    for (int i = ty; i < 32; i += 8) t[i][tx] = xp[i * NNODE + tx];
    __syncthreads();
    float* op = g_xt + ((b * NNODE + n0) * 64) + c0;
    #pragma unroll
    for (int i = ty; i < 32; i += 8) op[i * 64 + tx] = t[tx][i];
}

__global__ void k_norm() {
    int i = blockIdx.x * 256 + threadIdx.x;
    if (i >= NBATCH * NNODE) return;
    const float4* p = (const float4*)(g_xt + (size_t)i * 64);
    float s = 0.f;
    #pragma unroll
    for (int j = 0; j < 16; j++) {
        float4 v = p[j];
        s += v.x * v.x + v.y * v.y + v.z * v.z + v.w * v.w;
    }
    g_snorm[i] = sqrtf(s);
}

// ---------------- Gram + threshold -> adjacency bits (triangular, both orientations) ----
__global__ void __launch_bounds__(256, 2) k_gram(const float* __restrict__ x) {
    __shared__ __align__(16) float As[32][128];
    __shared__ __align__(16) float Bs[32][128];
    __shared__ float sns[128], pms[128];

    int b = blockIdx.z;
    int xid = blockIdx.x;
    int bj = (int)((sqrtf(8.f * xid + 1.f) - 1.f) * 0.5f);
    while ((bj + 1) * (bj + 2) / 2 <= xid) bj++;
    while (bj * (bj + 1) / 2 > xid) bj--;
    int bi = xid - bj * (bj + 1) / 2;
    int n0 = bi * 128, m0 = bj * 128;

    int t = threadIdx.x;
    if (t < 128) sns[t] = g_snorm[b * NNODE + n0 + t];
    else         pms[t - 128] = THR * g_snorm[b * NNODE + m0 + (t - 128)];

    int warp = t >> 5, lane = t & 31;
    int r = lane >> 3, c3 = lane & 7;
    int warpn = (warp >> 1) * 32;
    int nb = warpn + r * 8;
    int mwarp = (warp & 1) * 64;
    int mb = mwarp + c3 * 4;

    ull acc[8][4];
    #pragma unroll
    for (int i = 0; i < 8; i++)
        #pragma unroll
        for (int p = 0; p < 4; p++) acc[i][p] = 0ULL;

    const float* xa = x + (size_t)(b * 64) * NNODE;

    for (int kc = 0; kc < 2; kc++) {
        __syncthreads();
        #pragma unroll
        for (int i = 0; i < 4; i++) {
            int f4 = t + i * 256;
            int row = f4 >> 5, c4 = f4 & 31;
            const float* src = xa + (size_t)(kc * 32 + row) * NNODE;
            *(float4*)&As[row][c4 * 4] = *(const float4*)(src + n0 + c4 * 4);
            *(float4*)&Bs[row][c4 * 4] = *(const float4*)(src + m0 + c4 * 4);
        }
        __syncthreads();
        #pragma unroll 8
        for (int k = 0; k < 32; k++) {
            float4 a0 = *(const float4*)&As[k][nb];
            float4 a1 = *(const float4*)&As[k][nb + 4];
            ulonglong2 b0 = *(const ulonglong2*)&Bs[k][mb];
            ulonglong2 b1 = *(const ulonglong2*)&Bs[k][mb + 32];
            float av[8] = {a0.x, a0.y, a0.z, a0.w, a1.x, a1.y, a1.z, a1.w};
            #pragma unroll
            for (int i = 0; i < 8; i++) {
                ull a2 = pack2(av[i]);
                fma2(acc[i][0], a2, b0.x);
                fma2(acc[i][1], a2, b0.y);
                fma2(acc[i][2], a2, b1.x);
                fma2(acc[i][3], a2, b1.y);
            }
        }
    }

    float pmv[8];
    #pragma unroll
    for (int j = 0; j < 4; j++) {
        pmv[j]     = pms[mwarp + c3 * 4 + j];
        pmv[4 + j] = pms[mwarp + 32 + c3 * 4 + j];
    }
    unsigned bytesT[8];
    #pragma unroll
    for (int j = 0; j < 8; j++) bytesT[j] = 0u;

    int bw = (m0 + mwarp) >> 5;
    int nw = (n0 + warpn) >> 5;

    #pragma unroll
    for (int i = 0; i < 8; i++) {
        float sni = sns[nb + i];
        F2U q0, q1, q2, q3;
        q0.u = acc[i][0]; q1.u = acc[i][1]; q2.u = acc[i][2]; q3.u = acc[i][3];
        unsigned c0 = q0.f.x > sni * pmv[0];
        unsigned c1 = q0.f.y > sni * pmv[1];
        unsigned c2 = q1.f.x > sni * pmv[2];
        unsigned c3b = q1.f.y > sni * pmv[3];
        unsigned c4 = q2.f.x > sni * pmv[4];
        unsigned c5 = q2.f.y > sni * pmv[5];
        unsigned c6 = q3.f.x > sni * pmv[6];
        unsigned c7 = q3.f.y > sni * pmv[7];
        unsigned v0 = (c0 | (c1 << 1) | (c2 << 2) | (c3b << 3)) << (c3 * 4);
        unsigned v1 = (c4 | (c5 << 1) | (c6 << 2) | (c7 << 3)) << (c3 * 4);
        bytesT[0] |= c0 << i;  bytesT[1] |= c1 << i;
        bytesT[2] |= c2 << i;  bytesT[3] |= c3b << i;
        bytesT[4] |= c4 << i;  bytesT[5] |= c5 << i;
        bytesT[6] |= c6 << i;  bytesT[7] |= c7 << i;
        #pragma unroll
        for (int s = 1; s <= 4; s <<= 1) {
            v0 |= __shfl_xor_sync(0xffffffffu, v0, s);
            v1 |= __shfl_xor_sync(0xffffffffu, v1, s);
        }
        if (c3 == 0) {
            int gn = n0 + nb + i;
            g_adjT[((size_t)b * 128 + bw)     * NNODE + gn] = v0;
            g_adjT[((size_t)b * 128 + bw + 1) * NNODE + gn] = v1;
        }
    }
    #pragma unroll
    for (int jj = 0; jj < 8; jj++) {
        unsigned v = bytesT[jj] << (r * 8);
        v |= __shfl_xor_sync(0xffffffffu, v, 8);
        v |= __shfl_xor_sync(0xffffffffu, v, 16);
        if (r == 0) {
            int mg = m0 + mwarp + ((jj < 4) ? (c3 * 4 + jj) : (32 + c3 * 4 + jj - 4));
            g_adjT[((size_t)b * 128 + nw) * NNODE + mg] = v;
        }
    }
}

// ---------------- degree -> dinv (coalesced: warp per 32 nodes) ----------------
__global__ void k_deg() {
    int gw = blockIdx.x * 8 + (threadIdx.x >> 5);   // warp id, 512 total
    int lane = threadIdx.x & 31;
    int gi = gw * 32 + lane;                        // node over B*N
    int b = gi >> 12, nl = gi & 4095;
    const unsigned* p = g_adjT + (size_t)b * 128 * NNODE + nl;
    int c = 0;
    #pragma unroll 8
    for (int w = 0; w < 128; w++) c += __popc(p[(size_t)w * NNODE]);
    g_dinv[gi] = 1.0f / sqrtf((float)c);
}

// ---------------- split: xs = bf16_split(xin * dinv_m) ----------------
__global__ void k_split(int layer) {
    int i = blockIdx.x * 256 + threadIdx.x;   // 262144 quads
    const float* xin = (layer == 0) ? g_xt : g_x1;
    int node = i >> 4, c4 = (i & 15) * 4;
    float d = g_dinv[node];
    float4 v = *(const float4*)(xin + (size_t)node * 64 + c4);
    v.x *= d; v.y *= d; v.z *= d; v.w *= d;
    __nv_bfloat16 h0 = __float2bfloat16_rn(v.x);
    __nv_bfloat16 h1 = __float2bfloat16_rn(v.y);
    __nv_bfloat16 h2 = __float2bfloat16_rn(v.z);
    __nv_bfloat16 h3 = __float2bfloat16_rn(v.w);
    __nv_bfloat16 l0 = __float2bfloat16_rn(v.x - __bfloat162float(h0));
    __nv_bfloat16 l1 = __float2bfloat16_rn(v.y - __bfloat162float(h1));
    __nv_bfloat16 l2 = __float2bfloat16_rn(v.z - __bfloat162float(h2));
    __nv_bfloat16 l3 = __float2bfloat16_rn(v.w - __bfloat162float(h3));
    unsigned short* o = g_xs + (size_t)node * 128 + c4;
    ushort4 hh, ll;
    hh.x = *(unsigned short*)&h0; hh.y = *(unsigned short*)&h1;
    hh.z = *(unsigned short*)&h2; hh.w = *(unsigned short*)&h3;
    ll.x = *(unsigned short*)&l0; ll.y = *(unsigned short*)&l1;
    ll.z = *(unsigned short*)&l2; ll.w = *(unsigned short*)&l3;
    *(ushort4*)o        = hh;
    *(ushort4*)(o + 64) = ll;
}

// ---------------- diffusion GEMM: lx = dinv_n * (A_bits @ xs) via bf16 mma ----------------
// Block: 128 thr = 4 warps; block tile 64 rows x 128 f; warp 16 rows x 128 f.
// K loop over m in 64-chunks (2 adjacency words). A frags expanded from bits in
// registers; B frags via ldmatrix.x4.trans from padded smem tile. hi/lo column
// halves summed in the fragment epilogue.
__global__ void __launch_bounds__(128) k_mm() {
    __shared__ __align__(16) unsigned short bs[2][64][SP];   // 2 x 17408 B

    int b = blockIdx.y, n0 = blockIdx.x * 64;
    int t = threadIdx.x, wr = t >> 5, lane = t & 31;
    int g = lane >> 2, tq = lane & 3;
    int rl8 = (lane & 7) + ((lane >> 3) & 1) * 8;   // ldmatrix source row within k16
    int fg  = (lane >> 4) * 8;                      // ldmatrix f offset (8 bf16)

    float cc[16][4];
    #pragma unroll
    for (int j = 0; j < 16; j++)
        #pragma unroll
        for (int q = 0; q < 4; q++) cc[j][q] = 0.f;

    const unsigned short* xsb = g_xs + (size_t)b * NNODE * 128;
    const unsigned* pa = g_adjT + (size_t)b * 128 * NNODE + (n0 + wr * 16 + g);
    const unsigned* pa8 = pa + 8;

    // staging map: row = (t>>4) + 8*pass, chunk = t&15 (16B each)
    int srow = t >> 4, schk = t & 15;

    unsigned sbase[2];
    sbase[0] = (unsigned)__cvta_generic_to_shared(&bs[0][0][0]);
    sbase[1] = (unsigned)__cvta_generic_to_shared(&bs[1][0][0]);

    // prefetch chunk 0 B data
    float4 pf[8];
    #pragma unroll
    for (int ps = 0; ps < 8; ps++)
        pf[ps] = *(const float4*)(xsb + (size_t)(srow + ps * 8) * 128 + schk * 8);
    // stage chunk 0
    #pragma unroll
    for (int ps = 0; ps < 8; ps++)
        *(float4*)&bs[0][srow + ps * 8][schk * 8] = pf[ps];
    // prefetch chunk 1 B data
    #pragma unroll
    for (int ps = 0; ps < 8; ps++)
        pf[ps] = *(const float4*)(xsb + (size_t)(64 + srow + ps * 8) * 128 + schk * 8);
    // adjacency words for chunk 0
    unsigned w0a = pa[0], w1a = pa[(size_t)4096];
    unsigned w0b = pa8[0], w1b = pa8[(size_t)4096];

    for (int c = 0; c < 64; c++) {
        __syncthreads();
        // stage next chunk into other buffer; prefetch chunk c+2
        if (c + 1 < 64) {
            #pragma unroll
            for (int ps = 0; ps < 8; ps++)
                *(float4*)&bs[(c + 1) & 1][srow + ps * 8][schk * 8] = pf[ps];
            if (c + 2 < 64) {
                #pragma unroll
                for (int ps = 0; ps < 8; ps++)
                    pf[ps] = *(const float4*)(xsb + (size_t)((c + 2) * 64 + srow + ps * 8) * 128 + schk * 8);
            }
        }
        // prefetch next adjacency words
        unsigned nw0a = 0, nw1a = 0, nw0b = 0, nw1b = 0;
        if (c + 1 < 64) {
            nw0a = pa[(size_t)(2 * c + 2) * 4096];
            nw1a = pa[(size_t)(2 * c + 3) * 4096];
            nw0b = pa8[(size_t)(2 * c + 2) * 4096];
            nw1b = pa8[(size_t)(2 * c + 3) * 4096];
        }
        unsigned bb = sbase[c & 1];
        #pragma unroll
        for (int q = 0; q < 4; q++) {
            unsigned wA = (q < 2) ? w0a : w1a;
            unsigned wB = (q < 2) ? w0b : w1b;
            int s = ((q & 1) << 4) + 2 * tq;
            uint a0 = bfpair((wA >> s) & 3u);
            uint a2 = bfpair((wA >> (s + 8)) & 3u);
            uint a1 = bfpair((wB >> s) & 3u);
            uint a3 = bfpair((wB >> (s + 8)) & 3u);
            unsigned baddr = bb + ((q * 16 + rl8) * SP + fg) * 2;
            #pragma unroll
            for (int p = 0; p < 8; p++) {
                uint r0, r1, r2, r3;
                asm volatile(
                    "ldmatrix.sync.aligned.m8n8.x4.trans.shared.b16 {%0,%1,%2,%3}, [%4];"
                    : "=r"(r0), "=r"(r1), "=r"(r2), "=r"(r3)
                    : "r"(baddr + (unsigned)(p * 32)));
                asm volatile(
                    "mma.sync.aligned.m16n8k16.row.col.f32.bf16.bf16.f32 "
                    "{%0,%1,%2,%3}, {%4,%5,%6,%7}, {%8,%9}, {%0,%1,%2,%3};"
                    : "+f"(cc[2 * p][0]), "+f"(cc[2 * p][1]), "+f"(cc[2 * p][2]), "+f"(cc[2 * p][3])
                    : "r"(a0), "r"(a1), "r"(a2), "r"(a3), "r"(r0), "r"(r1));
                asm volatile(
                    "mma.sync.aligned.m16n8k16.row.col.f32.bf16.bf16.f32 "
                    "{%0,%1,%2,%3}, {%4,%5,%6,%7}, {%8,%9}, {%0,%1,%2,%3};"
                    : "+f"(cc[2 * p + 1][0]), "+f"(cc[2 * p + 1][1]), "+f"(cc[2 * p + 1][2]), "+f"(cc[2 * p + 1][3])
                    : "r"(a0), "r"(a1), "r"(a2), "r"(a3), "r"(r2), "r"(r3));
            }
        }
        w0a = nw0a; w1a = nw1a; w0b = nw0b; w1b = nw1b;
    }

    // epilogue: combine hi (tiles 0-7) + lo (tiles 8-15), scale by dinv_n, store
    int row0 = n0 + wr * 16 + g;
    float dn0 = g_dinv[b * NNODE + row0];
    float dn1 = g_dinv[b * NNODE + row0 + 8];
    float* o0 = g_lx + (size_t)(b * NNODE + row0) * 64;
    #pragma unroll
    for (int j = 0; j < 8; j++) {
        int col = j * 8 + 2 * tq;
        float2 u0 = make_float2((cc[j][0] + cc[j + 8][0]) * dn0,
                                (cc[j][1] + cc[j + 8][1]) * dn0);
        float2 u1 = make_float2((cc[j][2] + cc[j + 8][2]) * dn1,
                                (cc[j][3] + cc[j + 8][3]) * dn1);
        *(float2*)(o0 + col)           = u0;
        *(float2*)(o0 + 8 * 64 + col)  = u1;
    }
}

// ---------------- FC + instance-norm + relu ----------------
__global__ void __launch_bounds__(256) k_fc(const float* __restrict__ W,
                                            float* __restrict__ out_final,
                                            int layer) {
    __shared__ __align__(16) float lxs[64][72];
    __shared__ __align__(16) float ws[64][64];

    float* xout = (layer == 0) ? g_x1 : out_final;

    int b = blockIdx.y, n0 = blockIdx.x * 64;
    int t = threadIdx.x;
    int n = t >> 2, f0 = (t & 3) * 16;

    {
        const float4* g = (const float4*)(g_lx + (size_t)(b * NNODE + n0 + (t >> 2)) * NCH + (t & 3) * 16);
        float4* s = (float4*)&lxs[t >> 2][(t & 3) * 16];
        #pragma unroll
        for (int j = 0; j < 4; j++) s[j] = g[j];
        const float4* gw = (const float4*)(W + (t >> 2) * 64 + (t & 3) * 16);
        float4* sw = (float4*)&ws[t >> 2][(t & 3) * 16];
        #pragma unroll
        for (int j = 0; j < 4; j++) sw[j] = gw[j];
    }
    __syncthreads();

    ull h[8];
    #pragma unroll
    for (int j = 0; j < 8; j++) h[j] = 0ULL;
    #pragma unroll 8
    for (int c = 0; c < 64; c++) {
        ull a2 = pack2(lxs[n][c]);
        ulonglong2 w0 = *(const ulonglong2*)&ws[c][f0];
        ulonglong2 w1 = *(const ulonglong2*)&ws[c][f0 + 4];
        ulonglong2 w2 = *(const ulonglong2*)&ws[c][f0 + 8];
        ulonglong2 w3 = *(const ulonglong2*)&ws[c][f0 + 12];
        fma2(h[0], a2, w0.x); fma2(h[1], a2, w0.y);
        fma2(h[2], a2, w1.x); fma2(h[3], a2, w1.y);
        fma2(h[4], a2, w2.x); fma2(h[5], a2, w2.y);
        fma2(h[6], a2, w3.x); fma2(h[7], a2, w3.y);
    }
    float hv[16];
    #pragma unroll
    for (int j = 0; j < 8; j++) { F2U u; u.u = h[j]; hv[2 * j] = u.f.x; hv[2 * j + 1] = u.f.y; }

    float s = 0.f;
    #pragma unroll
    for (int j = 0; j < 16; j++) s += hv[j];
    s += __shfl_xor_sync(0xffffffffu, s, 1);
    s += __shfl_xor_sync(0xffffffffu, s, 2);
    float mean = s * (1.f / 64.f);
    float vq = 0.f;
    #pragma unroll
    for (int j = 0; j < 16; j++) { float d = hv[j] - mean; vq += d * d; }
    vq += __shfl_xor_sync(0xffffffffu, vq, 1);
    vq += __shfl_xor_sync(0xffffffffu, vq, 2);
    float inv = 1.0f / sqrtf(vq * (1.f / 64.f) + EPSI);

    float4* op = (float4*)(xout + (size_t)(b * NNODE + n0 + n) * 64 + f0);
    #pragma unroll
    for (int q = 0; q < 4; q++) {
        float4 o;
        o.x = fmaxf((hv[4 * q + 0] - mean) * inv, 0.f);
        o.y = fmaxf((hv[4 * q + 1] - mean) * inv, 0.f);
        o.z = fmaxf((hv[4 * q + 2] - mean) * inv, 0.f);
        o.w = fmaxf((hv[4 * q + 3] - mean) * inv, 0.f);
        op[q] = o;
    }
}

// ---------------- launch ----------------
extern "C" void kernel_launch(void* const* d_in, const int* in_sizes, int n_in,
                              void* d_out, int out_size) {
    const float* x  = (const float*)d_in[0];
    const float* W0 = (const float*)d_in[1];
    const float* W1 = (const float*)d_in[2];
    float* out = (float*)d_out;

    k_transpose<<<dim3(128, 2, 4), dim3(32, 8)>>>(x);
    k_norm<<<64, 256>>>();
    k_gram<<<dim3(528, 1, 4), 256>>>(x);
    k_deg<<<64, 256>>>();
    k_split<<<1024, 256>>>(0);
    k_mm<<<dim3(64, 4), 128>>>();
    k_fc<<<dim3(64, 4), 256>>>(W0, nullptr, 0);
    k_split<<<1024, 256>>>(1);
    k_mm<<<dim3(64, 4), 128>>>();
    k_fc<<<dim3(64, 4), 256>>>(W1, out, 1);
}